// round 3
// baseline (speedup 1.0000x reference)
#include <cuda_runtime.h>

#define NN  20000
#define FIN 64
#define NH  4
#define NC  128
#define HC  512
#define NE  320000
#define ET  (NE + NN)
#define FTS 128

// ---------------- scratch (device globals; no allocation allowed) ----------
__device__ __align__(16) float g_bufH[(size_t)NN * HC];   // pre-bias h of current layer
__device__ __align__(16) float g_bufA[(size_t)NN * HC];   // layer output (post relu+bias)
__device__ __align__(16) float g_bufC[(size_t)NN * FTS];  // head hidden
__device__ float g_asrc[NN * NH];
__device__ float g_adst[NN * NH];
__device__ float g_edot[8];           // [layer*4 + head]
__device__ int   g_rowptr[NN + 1];
__device__ int   g_cnt[NN];
__device__ int   g_col[ET];
__device__ __align__(16) float g_ewt[ET];
__device__ float g_part[256];
__device__ float g_mean;

// ---------------- mean(edge_weights) --------------------------------------
__global__ void k_msum(const float* __restrict__ ew) {
    __shared__ float sh[256];
    float s = 0.f;
    for (int i = blockIdx.x * 256 + threadIdx.x; i < NE; i += 256 * 256) s += ew[i];
    sh[threadIdx.x] = s; __syncthreads();
    for (int off = 128; off; off >>= 1) {
        if (threadIdx.x < off) sh[threadIdx.x] += sh[threadIdx.x + off];
        __syncthreads();
    }
    if (threadIdx.x == 0) g_part[blockIdx.x] = sh[0];
}
__global__ void k_mfin() {
    __shared__ float sh[256];
    sh[threadIdx.x] = g_part[threadIdx.x]; __syncthreads();
    for (int off = 128; off; off >>= 1) {
        if (threadIdx.x < off) sh[threadIdx.x] += sh[threadIdx.x + off];
        __syncthreads();
    }
    if (threadIdx.x == 0) g_mean = sh[0] * (1.0f / NE);
}

// ---------------- CSR build ------------------------------------------------
__global__ void k_zero_cnt() {
    int i = blockIdx.x * blockDim.x + threadIdx.x;
    if (i < NN) g_cnt[i] = 0;
}
// edge_index arrives as int32 [2, NE] (JAX x64 disabled -> int64 request is int32)
__global__ void k_hist(const int* __restrict__ ei) {
    int e = blockIdx.x * blockDim.x + threadIdx.x;
    if (e >= ET) return;
    int dst = (e < NE) ? ei[NE + e] : (e - NE);
    atomicAdd(&g_cnt[dst], 1);
}
__global__ void k_scan() {
    __shared__ int sh[1024];
    int t = threadIdx.x;
    int carry = 0;
    for (int base = 0; base < NN; base += 1024) {
        int idx = base + t;
        int v = (idx < NN) ? g_cnt[idx] : 0;
        sh[t] = v; __syncthreads();
        for (int off = 1; off < 1024; off <<= 1) {
            int x = (t >= off) ? sh[t - off] : 0;
            __syncthreads();
            sh[t] += x;
            __syncthreads();
        }
        if (idx < NN) g_rowptr[idx] = carry + sh[t] - v;
        carry += sh[1023];
        __syncthreads();
    }
    if (t == 0) g_rowptr[NN] = carry;
}
__global__ void k_scatter(const int* __restrict__ ei,
                          const float* __restrict__ ew) {
    int e = blockIdx.x * blockDim.x + threadIdx.x;
    if (e >= ET) return;
    int src, dst; float w;
    if (e < NE) { src = ei[e]; dst = ei[NE + e]; w = ew[e]; }
    else        { src = dst = e - NE; w = g_mean; }
    int pos = g_rowptr[dst] + atomicAdd(&g_cnt[dst], 1);
    g_col[pos] = src;
    g_ewt[pos] = w;
}

// ---------------- edge-attention dot precompute -----------------------------
// alpha_edge[e,h] = ew[e] * sum_c(We[h*C+c]*ae[h*C+c])
__global__ void k_edot(const float* __restrict__ We0, const float* __restrict__ ae0,
                       const float* __restrict__ We1, const float* __restrict__ ae1) {
    int w = threadIdx.x >> 5, lane = threadIdx.x & 31;
    const float* We = (w < 4) ? We0 : We1;
    const float* ae = (w < 4) ? ae0 : ae1;
    int hh = w & 3;
    float s = 0.f;
    for (int c = lane; c < NC; c += 32) s += We[hh * NC + c] * ae[hh * NC + c];
    #pragma unroll
    for (int off = 16; off; off >>= 1) s += __shfl_xor_sync(0xffffffffu, s, off);
    if (lane == 0) g_edot[w] = s;
}

// ---------------- SGEMM: C[M,Nn] = A[M,K] @ B[Nn,K]^T (+bias)(+relu) -------
// aSel: 0 = external pointer Aext, 1 = g_bufA
// cSel: 0 = g_bufH,  1 = g_bufC
__global__ void __launch_bounds__(256)
sgemm_nt(const float* __restrict__ Aext, int aSel, int cSel,
         const float* __restrict__ B, const float* __restrict__ bias,
         int M, int Nn, int K, int relu) {
    const float* __restrict__ A = (aSel == 0) ? Aext : (const float*)g_bufA;
    float* __restrict__ Cm = (cSel == 0) ? g_bufH : g_bufC;
    __shared__ float As[8][128];
    __shared__ float Bs[8][128];
    int tid = threadIdx.x;
    int tx = tid & 15, ty = tid >> 4;
    int row0 = blockIdx.y * 128, col0 = blockIdx.x * 128;
    int lr = tid >> 1;
    int lc = (tid & 1) << 2;
    float acc[8][8];
    #pragma unroll
    for (int i = 0; i < 8; i++)
        #pragma unroll
        for (int j = 0; j < 8; j++) acc[i][j] = 0.f;

    const float* Ap = A + (size_t)(row0 + lr) * K + lc;
    const float* Bp = B + (size_t)(col0 + lr) * K + lc;
    bool aval = (row0 + lr) < M;

    for (int k0 = 0; k0 < K; k0 += 8) {
        float4 av = aval ? *(const float4*)(Ap + k0) : make_float4(0.f, 0.f, 0.f, 0.f);
        float4 bv = *(const float4*)(Bp + k0);
        As[lc + 0][lr] = av.x; As[lc + 1][lr] = av.y;
        As[lc + 2][lr] = av.z; As[lc + 3][lr] = av.w;
        Bs[lc + 0][lr] = bv.x; Bs[lc + 1][lr] = bv.y;
        Bs[lc + 2][lr] = bv.z; Bs[lc + 3][lr] = bv.w;
        __syncthreads();
        #pragma unroll
        for (int k = 0; k < 8; k++) {
            float a[8], b[8];
            *(float4*)(a)     = *(const float4*)&As[k][ty * 8];
            *(float4*)(a + 4) = *(const float4*)&As[k][ty * 8 + 4];
            *(float4*)(b)     = *(const float4*)&Bs[k][tx * 8];
            *(float4*)(b + 4) = *(const float4*)&Bs[k][tx * 8 + 4];
            #pragma unroll
            for (int i = 0; i < 8; i++)
                #pragma unroll
                for (int j = 0; j < 8; j++) acc[i][j] += a[i] * b[j];
        }
        __syncthreads();
    }
    #pragma unroll
    for (int i = 0; i < 8; i++) {
        int r = row0 + ty * 8 + i;
        if (r >= M) break;
        #pragma unroll
        for (int j = 0; j < 8; j += 4) {
            int c = col0 + tx * 8 + j;
            float4 v;
            v.x = acc[i][j]; v.y = acc[i][j + 1]; v.z = acc[i][j + 2]; v.w = acc[i][j + 3];
            if (bias) {
                v.x += bias[c]; v.y += bias[c + 1]; v.z += bias[c + 2]; v.w += bias[c + 3];
            }
            if (relu) {
                v.x = fmaxf(v.x, 0.f); v.y = fmaxf(v.y, 0.f);
                v.z = fmaxf(v.z, 0.f); v.w = fmaxf(v.w, 0.f);
            }
            *(float4*)(Cm + (size_t)r * Nn + c) = v;
        }
    }
}

// ---------------- per-(node,head) attention coefficients -------------------
__global__ void k_attn(const float* __restrict__ a_s,
                       const float* __restrict__ a_d) {
    int w = (blockIdx.x * blockDim.x + threadIdx.x) >> 5;
    if (w >= NN * NH) return;
    int lane = threadIdx.x & 31;
    int n = w >> 2, hh = w & 3;
    const float4* hp = (const float4*)(g_bufH + (size_t)n * HC + hh * NC);
    const float4* sp = (const float4*)(a_s + hh * NC);
    const float4* dp = (const float4*)(a_d + hh * NC);
    float4 hv = hp[lane], sv = sp[lane], dv = dp[lane];
    float ps = hv.x * sv.x + hv.y * sv.y + hv.z * sv.z + hv.w * sv.w;
    float pd = hv.x * dv.x + hv.y * dv.y + hv.z * dv.z + hv.w * dv.w;
    #pragma unroll
    for (int off = 16; off; off >>= 1) {
        ps += __shfl_xor_sync(0xffffffffu, ps, off);
        pd += __shfl_xor_sync(0xffffffffu, pd, off);
    }
    if (lane == 0) { g_asrc[w] = ps; g_adst[w] = pd; }
}

// ---------------- per-dst softmax + weighted aggregation -------------------
// One warp per destination node. Lane layout: edge slot = lane>>2, head = lane&3.
// Softmax normalization is deferred: acc = sum_e p_e * h[src_e]; out = acc/s.
// Reads g_bufH, writes g_bufA.
__global__ void __launch_bounds__(256)
k_agg(const float* __restrict__ bias, int edotOff) {
    int w = (blockIdx.x * blockDim.x + threadIdx.x) >> 5;
    if (w >= NN) return;
    int lane = threadIdx.x & 31;
    int n = w;
    int beg = g_rowptr[n], end = g_rowptr[n + 1];
    int hh = lane & 3;
    float adn = g_adst[n * NH + hh];
    float ed = g_edot[edotOff + hh];

    // pass 1: per-head max of leaky_relu(logit)
    float lmax = -1e30f;
    for (int i = beg + (lane >> 2); i < end; i += 8) {
        int s = g_col[i];
        float l = g_asrc[s * NH + hh] + adn + g_ewt[i] * ed;
        l = (l > 0.f) ? l : 0.2f * l;
        lmax = fmaxf(lmax, l);
    }
    #pragma unroll
    for (int off = 4; off < 32; off <<= 1)
        lmax = fmaxf(lmax, __shfl_xor_sync(0xffffffffu, lmax, off));

    // pass 2: p = exp(l-max); accumulate p-weighted h[src]
    float4 acc0 = {0, 0, 0, 0}, acc1 = {0, 0, 0, 0}, acc2 = {0, 0, 0, 0}, acc3 = {0, 0, 0, 0};
    float psum = 0.f;
    for (int base = beg; base < end; base += 8) {
        int i = base + (lane >> 2);
        float p = 0.f; int s = 0;
        if (i < end) {
            s = g_col[i];
            float l = g_asrc[s * NH + hh] + adn + g_ewt[i] * ed;
            l = (l > 0.f) ? l : 0.2f * l;
            p = __expf(l - lmax);
        }
        psum += p;
        int nb = min(8, end - base);
        for (int j = 0; j < nb; j++) {
            int   sj = __shfl_sync(0xffffffffu, s, j * 4);
            float p0 = __shfl_sync(0xffffffffu, p, j * 4 + 0);
            float p1 = __shfl_sync(0xffffffffu, p, j * 4 + 1);
            float p2 = __shfl_sync(0xffffffffu, p, j * 4 + 2);
            float p3 = __shfl_sync(0xffffffffu, p, j * 4 + 3);
            const float4* hp = (const float4*)(g_bufH + (size_t)sj * HC);
            float4 v;
            v = hp[lane +  0]; acc0.x += v.x * p0; acc0.y += v.y * p0; acc0.z += v.z * p0; acc0.w += v.w * p0;
            v = hp[lane + 32]; acc1.x += v.x * p1; acc1.y += v.y * p1; acc1.z += v.z * p1; acc1.w += v.w * p1;
            v = hp[lane + 64]; acc2.x += v.x * p2; acc2.y += v.y * p2; acc2.z += v.z * p2; acc2.w += v.w * p2;
            v = hp[lane + 96]; acc3.x += v.x * p3; acc3.y += v.y * p3; acc3.z += v.z * p3; acc3.w += v.w * p3;
        }
    }
    #pragma unroll
    for (int off = 4; off < 32; off <<= 1)
        psum += __shfl_xor_sync(0xffffffffu, psum, off);
    float s0 = 1.f / (__shfl_sync(0xffffffffu, psum, 0) + 1e-16f);
    float s1 = 1.f / (__shfl_sync(0xffffffffu, psum, 1) + 1e-16f);
    float s2 = 1.f / (__shfl_sync(0xffffffffu, psum, 2) + 1e-16f);
    float s3 = 1.f / (__shfl_sync(0xffffffffu, psum, 3) + 1e-16f);

    float4* op = (float4*)(g_bufA + (size_t)n * HC);
    const float4* bp = (const float4*)bias;
    float4 bv, o;
    bv = bp[lane +  0];
    o.x = fmaxf(acc0.x * s0 + bv.x, 0.f); o.y = fmaxf(acc0.y * s0 + bv.y, 0.f);
    o.z = fmaxf(acc0.z * s0 + bv.z, 0.f); o.w = fmaxf(acc0.w * s0 + bv.w, 0.f);
    op[lane + 0] = o;
    bv = bp[lane + 32];
    o.x = fmaxf(acc1.x * s1 + bv.x, 0.f); o.y = fmaxf(acc1.y * s1 + bv.y, 0.f);
    o.z = fmaxf(acc1.z * s1 + bv.z, 0.f); o.w = fmaxf(acc1.w * s1 + bv.w, 0.f);
    op[lane + 32] = o;
    bv = bp[lane + 64];
    o.x = fmaxf(acc2.x * s2 + bv.x, 0.f); o.y = fmaxf(acc2.y * s2 + bv.y, 0.f);
    o.z = fmaxf(acc2.z * s2 + bv.z, 0.f); o.w = fmaxf(acc2.w * s2 + bv.w, 0.f);
    op[lane + 64] = o;
    bv = bp[lane + 96];
    o.x = fmaxf(acc3.x * s3 + bv.x, 0.f); o.y = fmaxf(acc3.y * s3 + bv.y, 0.f);
    o.z = fmaxf(acc3.z * s3 + bv.z, 0.f); o.w = fmaxf(acc3.w * s3 + bv.w, 0.f);
    op[lane + 96] = o;
}

// ---------------- final head: out[n] = dot(bufC[n], L1W) + L1b -------------
__global__ void k_final(const float* __restrict__ L1W, const float* __restrict__ L1b,
                        float* __restrict__ out) {
    int w = (blockIdx.x * blockDim.x + threadIdx.x) >> 5;
    if (w >= NN) return;
    int lane = threadIdx.x & 31;
    const float4* hp = (const float4*)(g_bufC + (size_t)w * FTS);
    const float4* wp = (const float4*)L1W;
    float4 h = hp[lane], ww = wp[lane];
    float s = h.x * ww.x + h.y * ww.y + h.z * ww.z + h.w * ww.w;
    #pragma unroll
    for (int off = 16; off; off >>= 1) s += __shfl_xor_sync(0xffffffffu, s, off);
    if (lane == 0) out[w] = s + L1b[0];
}

// ---------------- launch ----------------------------------------------------
extern "C" void kernel_launch(void* const* d_in, const int* in_sizes, int n_in,
                              void* d_out, int out_size) {
    const float* x   = (const float*)d_in[0];
    const int*   ei  = (const int*)d_in[1];     // int32 [2, NE]
    const float* ew  = (const float*)d_in[2];
    const float* W0  = (const float*)d_in[3];
    const float* as0 = (const float*)d_in[4];
    const float* ad0 = (const float*)d_in[5];
    const float* We0 = (const float*)d_in[6];
    const float* ae0 = (const float*)d_in[7];
    const float* b0  = (const float*)d_in[8];
    const float* W1  = (const float*)d_in[9];
    const float* as1 = (const float*)d_in[10];
    const float* ad1 = (const float*)d_in[11];
    const float* We1 = (const float*)d_in[12];
    const float* ae1 = (const float*)d_in[13];
    const float* b1  = (const float*)d_in[14];
    const float* L0W = (const float*)d_in[15];
    const float* L0b = (const float*)d_in[16];
    const float* L1W = (const float*)d_in[17];
    const float* L1b = (const float*)d_in[18];
    float* out = (float*)d_out;

    // ---- graph setup: mean, CSR by dst, edge-attention dots ----
    k_msum<<<256, 256>>>(ew);
    k_mfin<<<1, 256>>>();
    k_zero_cnt<<<(NN + 255) / 256, 256>>>();
    k_hist<<<(ET + 255) / 256, 256>>>(ei);
    k_scan<<<1, 1024>>>();
    k_zero_cnt<<<(NN + 255) / 256, 256>>>();
    k_scatter<<<(ET + 255) / 256, 256>>>(ei, ew);
    k_edot<<<1, 256>>>(We0, ae0, We1, ae1);

    dim3 gemmGrid512(4, (NN + 127) / 128);
    dim3 gemmGrid128(1, (NN + 127) / 128);

    // ---- GAT layer 0 ----
    sgemm_nt<<<gemmGrid512, 256>>>(x, 0, 0, W0, nullptr, NN, HC, FIN, 0);
    k_attn<<<(NN * NH + 7) / 8, 256>>>(as0, ad0);
    k_agg<<<(NN + 7) / 8, 256>>>(b0, 0);

    // ---- GAT layer 1 ----
    sgemm_nt<<<gemmGrid512, 256>>>(nullptr, 1, 0, W1, nullptr, NN, HC, HC, 0);
    k_attn<<<(NN * NH + 7) / 8, 256>>>(as1, ad1);
    k_agg<<<(NN + 7) / 8, 256>>>(b1, 4);

    // ---- MLP head ----
    sgemm_nt<<<gemmGrid128, 256>>>(nullptr, 1, 1, L0W, L0b, NN, FTS, HC, 1);
    k_final<<<(NN + 7) / 8, 256>>>(L1W, L1b, out);
}

// round 5
// speedup vs baseline: 1.3870x; 1.3870x over previous
#include <cuda_runtime.h>
#include <cstdint>
#include <mma.h>
using namespace nvcuda;

#define NN  20000
#define NP  20096               // 157 * 128, padded row count for GEMM tiles
#define FIN 64
#define NH  4
#define NC  128
#define HC  512
#define NE  320000
#define ET  (NE + NN)
#define FTS 128

// ---------------- scratch (device globals; no allocation allowed) ----------
__device__ __align__(16) float g_bufH[(size_t)NP * HC];   // pre-bias h of current layer
__device__ __align__(16) float g_bufA[(size_t)NP * HC];   // layer output (post relu+bias)
__device__ __align__(16) float g_bufC[(size_t)NP * FTS];  // head hidden (pre-bias/relu)
__device__ float g_asrc[NN * NH];
__device__ float g_adst[NN * NH];
__device__ float g_edot[8];           // [layer*4 + head]
__device__ int   g_rowptr[NN + 1];
__device__ int   g_cnt[NN];
__device__ int   g_col[ET];
__device__ __align__(16) float g_ewt[ET];
__device__ float g_part[256];
__device__ float g_mean;

// ---------------- mean(edge_weights) --------------------------------------
__global__ void k_msum(const float* __restrict__ ew) {
    __shared__ float sh[256];
    float s = 0.f;
    for (int i = blockIdx.x * 256 + threadIdx.x; i < NE; i += 256 * 256) s += ew[i];
    sh[threadIdx.x] = s; __syncthreads();
    for (int off = 128; off; off >>= 1) {
        if (threadIdx.x < off) sh[threadIdx.x] += sh[threadIdx.x + off];
        __syncthreads();
    }
    if (threadIdx.x == 0) g_part[blockIdx.x] = sh[0];
}
__global__ void k_mfin() {
    __shared__ float sh[256];
    sh[threadIdx.x] = g_part[threadIdx.x]; __syncthreads();
    for (int off = 128; off; off >>= 1) {
        if (threadIdx.x < off) sh[threadIdx.x] += sh[threadIdx.x + off];
        __syncthreads();
    }
    if (threadIdx.x == 0) g_mean = sh[0] * (1.0f / NE);
}

// ---------------- CSR build ------------------------------------------------
__global__ void k_zero_cnt() {
    int i = blockIdx.x * blockDim.x + threadIdx.x;
    if (i < NN) g_cnt[i] = 0;
}
// edge_index arrives as int32 [2, NE]
__global__ void k_hist(const int* __restrict__ ei) {
    int e = blockIdx.x * blockDim.x + threadIdx.x;
    if (e >= ET) return;
    int dst = (e < NE) ? ei[NE + e] : (e - NE);
    atomicAdd(&g_cnt[dst], 1);
}
__global__ void k_scan() {
    __shared__ int sh[1024];
    int t = threadIdx.x;
    int carry = 0;
    for (int base = 0; base < NN; base += 1024) {
        int idx = base + t;
        int v = (idx < NN) ? g_cnt[idx] : 0;
        sh[t] = v; __syncthreads();
        for (int off = 1; off < 1024; off <<= 1) {
            int x = (t >= off) ? sh[t - off] : 0;
            __syncthreads();
            sh[t] += x;
            __syncthreads();
        }
        if (idx < NN) g_rowptr[idx] = carry + sh[t] - v;
        carry += sh[1023];
        __syncthreads();
    }
    if (t == 0) g_rowptr[NN] = carry;
}
__global__ void k_scatter(const int* __restrict__ ei,
                          const float* __restrict__ ew) {
    int e = blockIdx.x * blockDim.x + threadIdx.x;
    if (e >= ET) return;
    int src, dst; float w;
    if (e < NE) { src = ei[e]; dst = ei[NE + e]; w = ew[e]; }
    else        { src = dst = e - NE; w = g_mean; }
    int pos = g_rowptr[dst] + atomicAdd(&g_cnt[dst], 1);
    g_col[pos] = src;
    g_ewt[pos] = w;
}

// ---------------- edge-attention dot precompute -----------------------------
__global__ void k_edot(const float* __restrict__ We0, const float* __restrict__ ae0,
                       const float* __restrict__ We1, const float* __restrict__ ae1) {
    int w = threadIdx.x >> 5, lane = threadIdx.x & 31;
    const float* We = (w < 4) ? We0 : We1;
    const float* ae = (w < 4) ? ae0 : ae1;
    int hh = w & 3;
    float s = 0.f;
    for (int c = lane; c < NC; c += 32) s += We[hh * NC + c] * ae[hh * NC + c];
    #pragma unroll
    for (int off = 16; off; off >>= 1) s += __shfl_xor_sync(0xffffffffu, s, off);
    if (lane == 0) g_edot[w] = s;
}

// ---------------- TF32 tensor-core GEMM: C = A[M,K] @ B[Nn,K]^T ------------
// aSel: 0 = Aext, 1 = g_bufA.  cSel: 0 = g_bufH, 1 = g_bufC.
// C buffers are padded to NP rows, so fragment stores need no bounds checks.
// A loads are guarded (zero-fill for rows >= M).
#define KC 16
__global__ void __launch_bounds__(256, 2)
tgemm(const float* __restrict__ Aext, int aSel, int cSel,
      const float* __restrict__ B, int M, int Nn, int K) {
    const float* __restrict__ A = aSel ? (const float*)g_bufA : Aext;
    float* __restrict__ Cm = cSel ? g_bufC : g_bufH;

    __shared__ float As[2][128][KC + 8];   // ld = 24
    __shared__ float Bs[2][128][KC + 8];

    int tid = threadIdx.x;
    int wid = tid >> 5;
    int row0 = blockIdx.y * 128, col0 = blockIdx.x * 128;
    int warp_m = (wid >> 2) * 64;          // 0 or 64
    int warp_n = (wid & 3) * 32;           // 0,32,64,96

    wmma::fragment<wmma::accumulator, 16, 16, 8, float> acc[4][2];
    #pragma unroll
    for (int i = 0; i < 4; i++)
        #pragma unroll
        for (int j = 0; j < 2; j++) wmma::fill_fragment(acc[i][j], 0.f);

    // per-thread load coords: 2 float4 per matrix per stage
    int r0 = tid >> 2;                     // 0..63  (+64 for second)
    int kq = (tid & 3) << 2;               // 0,4,8,12

    int T = K / KC;

    // prologue: stage 0
    {
        int k0 = 0;
        #pragma unroll
        for (int i = 0; i < 2; i++) {
            int r = r0 + i * 64;
            unsigned int sa = (unsigned int)__cvta_generic_to_shared(&As[0][r][kq]);
            const float* gp = A + (size_t)(row0 + r) * K + k0 + kq;
            if (row0 + r < M)
                asm volatile("cp.async.ca.shared.global [%0], [%1], 16;" :: "r"(sa), "l"(gp));
            else
                *(float4*)&As[0][r][kq] = make_float4(0.f, 0.f, 0.f, 0.f);
            unsigned int sb = (unsigned int)__cvta_generic_to_shared(&Bs[0][r][kq]);
            const float* gb = B + (size_t)(col0 + r) * K + k0 + kq;
            asm volatile("cp.async.ca.shared.global [%0], [%1], 16;" :: "r"(sb), "l"(gb));
        }
        asm volatile("cp.async.commit_group;");
    }

    for (int t = 0; t < T; t++) {
        int cur = t & 1;
        if (t + 1 < T) {
            int k0 = (t + 1) * KC, nxt = (t + 1) & 1;
            #pragma unroll
            for (int i = 0; i < 2; i++) {
                int r = r0 + i * 64;
                unsigned int sa = (unsigned int)__cvta_generic_to_shared(&As[nxt][r][kq]);
                const float* gp = A + (size_t)(row0 + r) * K + k0 + kq;
                if (row0 + r < M)
                    asm volatile("cp.async.ca.shared.global [%0], [%1], 16;" :: "r"(sa), "l"(gp));
                else
                    *(float4*)&As[nxt][r][kq] = make_float4(0.f, 0.f, 0.f, 0.f);
                unsigned int sb = (unsigned int)__cvta_generic_to_shared(&Bs[nxt][r][kq]);
                const float* gb = B + (size_t)(col0 + r) * K + k0 + kq;
                asm volatile("cp.async.ca.shared.global [%0], [%1], 16;" :: "r"(sb), "l"(gb));
            }
            asm volatile("cp.async.commit_group;");
            asm volatile("cp.async.wait_group 1;");
        } else {
            asm volatile("cp.async.wait_group 0;");
        }
        __syncthreads();

        #pragma unroll
        for (int kk = 0; kk < KC; kk += 8) {
            wmma::fragment<wmma::matrix_a, 16, 16, 8, wmma::precision::tf32, wmma::row_major> af[4];
            wmma::fragment<wmma::matrix_b, 16, 16, 8, wmma::precision::tf32, wmma::col_major> bf[2];
            #pragma unroll
            for (int i = 0; i < 4; i++) {
                wmma::load_matrix_sync(af[i], &As[cur][warp_m + i * 16][kk], KC + 8);
                #pragma unroll
                for (int e = 0; e < af[i].num_elements; e++)
                    af[i].x[e] = wmma::__float_to_tf32(af[i].x[e]);
            }
            #pragma unroll
            for (int j = 0; j < 2; j++) {
                wmma::load_matrix_sync(bf[j], &Bs[cur][warp_n + j * 16][kk], KC + 8);
                #pragma unroll
                for (int e = 0; e < bf[j].num_elements; e++)
                    bf[j].x[e] = wmma::__float_to_tf32(bf[j].x[e]);
            }
            #pragma unroll
            for (int i = 0; i < 4; i++)
                #pragma unroll
                for (int j = 0; j < 2; j++)
                    wmma::mma_sync(acc[i][j], af[i], bf[j], acc[i][j]);
        }
        __syncthreads();
    }

    #pragma unroll
    for (int i = 0; i < 4; i++)
        #pragma unroll
        for (int j = 0; j < 2; j++)
            wmma::store_matrix_sync(Cm + (size_t)(row0 + warp_m + i * 16) * Nn
                                       + col0 + warp_n + j * 16,
                                    acc[i][j], Nn, wmma::mem_row_major);
}

// ---------------- per-(node,head) attention coefficients -------------------
__global__ void k_attn(const float* __restrict__ a_s,
                       const float* __restrict__ a_d) {
    int w = (blockIdx.x * blockDim.x + threadIdx.x) >> 5;
    if (w >= NN * NH) return;
    int lane = threadIdx.x & 31;
    int n = w >> 2, hh = w & 3;
    const float4* hp = (const float4*)(g_bufH + (size_t)n * HC + hh * NC);
    const float4* sp = (const float4*)(a_s + hh * NC);
    const float4* dp = (const float4*)(a_d + hh * NC);
    float4 hv = hp[lane], sv = sp[lane], dv = dp[lane];
    float ps = hv.x * sv.x + hv.y * sv.y + hv.z * sv.z + hv.w * sv.w;
    float pd = hv.x * dv.x + hv.y * dv.y + hv.z * dv.z + hv.w * dv.w;
    #pragma unroll
    for (int off = 16; off; off >>= 1) {
        ps += __shfl_xor_sync(0xffffffffu, ps, off);
        pd += __shfl_xor_sync(0xffffffffu, pd, off);
    }
    if (lane == 0) { g_asrc[w] = ps; g_adst[w] = pd; }
}

// ---------------- per-dst softmax + weighted aggregation -------------------
__global__ void __launch_bounds__(256)
k_agg(const float* __restrict__ bias, int edotOff) {
    int w = (blockIdx.x * blockDim.x + threadIdx.x) >> 5;
    if (w >= NN) return;
    int lane = threadIdx.x & 31;
    int n = w;
    int beg = g_rowptr[n], end = g_rowptr[n + 1];
    int hh = lane & 3;
    float adn = g_adst[n * NH + hh];
    float ed = g_edot[edotOff + hh];

    float lmax = -1e30f;
    for (int i = beg + (lane >> 2); i < end; i += 8) {
        int s = g_col[i];
        float l = g_asrc[s * NH + hh] + adn + g_ewt[i] * ed;
        l = (l > 0.f) ? l : 0.2f * l;
        lmax = fmaxf(lmax, l);
    }
    #pragma unroll
    for (int off = 4; off < 32; off <<= 1)
        lmax = fmaxf(lmax, __shfl_xor_sync(0xffffffffu, lmax, off));

    float4 acc0 = {0, 0, 0, 0}, acc1 = {0, 0, 0, 0}, acc2 = {0, 0, 0, 0}, acc3 = {0, 0, 0, 0};
    float psum = 0.f;
    for (int base = beg; base < end; base += 8) {
        int i = base + (lane >> 2);
        float p = 0.f; int s = 0;
        if (i < end) {
            s = g_col[i];
            float l = g_asrc[s * NH + hh] + adn + g_ewt[i] * ed;
            l = (l > 0.f) ? l : 0.2f * l;
            p = __expf(l - lmax);
        }
        psum += p;
        int nb = min(8, end - base);
        for (int j = 0; j < nb; j++) {
            int   sj = __shfl_sync(0xffffffffu, s, j * 4);
            float p0 = __shfl_sync(0xffffffffu, p, j * 4 + 0);
            float p1 = __shfl_sync(0xffffffffu, p, j * 4 + 1);
            float p2 = __shfl_sync(0xffffffffu, p, j * 4 + 2);
            float p3 = __shfl_sync(0xffffffffu, p, j * 4 + 3);
            const float4* hp = (const float4*)(g_bufH + (size_t)sj * HC);
            float4 v;
            v = hp[lane +  0]; acc0.x += v.x * p0; acc0.y += v.y * p0; acc0.z += v.z * p0; acc0.w += v.w * p0;
            v = hp[lane + 32]; acc1.x += v.x * p1; acc1.y += v.y * p1; acc1.z += v.z * p1; acc1.w += v.w * p1;
            v = hp[lane + 64]; acc2.x += v.x * p2; acc2.y += v.y * p2; acc2.z += v.z * p2; acc2.w += v.w * p2;
            v = hp[lane + 96]; acc3.x += v.x * p3; acc3.y += v.y * p3; acc3.z += v.z * p3; acc3.w += v.w * p3;
        }
    }
    #pragma unroll
    for (int off = 4; off < 32; off <<= 1)
        psum += __shfl_xor_sync(0xffffffffu, psum, off);
    float s0 = 1.f / (__shfl_sync(0xffffffffu, psum, 0) + 1e-16f);
    float s1 = 1.f / (__shfl_sync(0xffffffffu, psum, 1) + 1e-16f);
    float s2 = 1.f / (__shfl_sync(0xffffffffu, psum, 2) + 1e-16f);
    float s3 = 1.f / (__shfl_sync(0xffffffffu, psum, 3) + 1e-16f);

    float4* op = (float4*)(g_bufA + (size_t)n * HC);
    const float4* bp = (const float4*)bias;
    float4 bv, o;
    bv = bp[lane +  0];
    o.x = fmaxf(acc0.x * s0 + bv.x, 0.f); o.y = fmaxf(acc0.y * s0 + bv.y, 0.f);
    o.z = fmaxf(acc0.z * s0 + bv.z, 0.f); o.w = fmaxf(acc0.w * s0 + bv.w, 0.f);
    op[lane + 0] = o;
    bv = bp[lane + 32];
    o.x = fmaxf(acc1.x * s1 + bv.x, 0.f); o.y = fmaxf(acc1.y * s1 + bv.y, 0.f);
    o.z = fmaxf(acc1.z * s1 + bv.z, 0.f); o.w = fmaxf(acc1.w * s1 + bv.w, 0.f);
    op[lane + 32] = o;
    bv = bp[lane + 64];
    o.x = fmaxf(acc2.x * s2 + bv.x, 0.f); o.y = fmaxf(acc2.y * s2 + bv.y, 0.f);
    o.z = fmaxf(acc2.z * s2 + bv.z, 0.f); o.w = fmaxf(acc2.w * s2 + bv.w, 0.f);
    op[lane + 64] = o;
    bv = bp[lane + 96];
    o.x = fmaxf(acc3.x * s3 + bv.x, 0.f); o.y = fmaxf(acc3.y * s3 + bv.y, 0.f);
    o.z = fmaxf(acc3.z * s3 + bv.z, 0.f); o.w = fmaxf(acc3.w * s3 + bv.w, 0.f);
    op[lane + 96] = o;
}

// ---------------- final head: out[n] = relu(c+b) . L1W + L1b ---------------
__global__ void k_final(const float* __restrict__ L0b,
                        const float* __restrict__ L1W, const float* __restrict__ L1b,
                        float* __restrict__ out) {
    int w = (blockIdx.x * blockDim.x + threadIdx.x) >> 5;
    if (w >= NN) return;
    int lane = threadIdx.x & 31;
    const float4* hp = (const float4*)(g_bufC + (size_t)w * FTS);
    const float4* bp = (const float4*)L0b;
    const float4* wp = (const float4*)L1W;
    float4 h = hp[lane], bb = bp[lane], ww = wp[lane];
    float s = fmaxf(h.x + bb.x, 0.f) * ww.x + fmaxf(h.y + bb.y, 0.f) * ww.y
            + fmaxf(h.z + bb.z, 0.f) * ww.z + fmaxf(h.w + bb.w, 0.f) * ww.w;
    #pragma unroll
    for (int off = 16; off; off >>= 1) s += __shfl_xor_sync(0xffffffffu, s, off);
    if (lane == 0) out[w] = s + L1b[0];
}

// ---------------- launch ----------------------------------------------------
extern "C" void kernel_launch(void* const* d_in, const int* in_sizes, int n_in,
                              void* d_out, int out_size) {
    const float* x   = (const float*)d_in[0];
    const int*   ei  = (const int*)d_in[1];     // int32 [2, NE]
    const float* ew  = (const float*)d_in[2];
    const float* W0  = (const float*)d_in[3];
    const float* as0 = (const float*)d_in[4];
    const float* ad0 = (const float*)d_in[5];
    const float* We0 = (const float*)d_in[6];
    const float* ae0 = (const float*)d_in[7];
    const float* b0  = (const float*)d_in[8];
    const float* W1  = (const float*)d_in[9];
    const float* as1 = (const float*)d_in[10];
    const float* ad1 = (const float*)d_in[11];
    const float* We1 = (const float*)d_in[12];
    const float* ae1 = (const float*)d_in[13];
    const float* b1  = (const float*)d_in[14];
    const float* L0W = (const float*)d_in[15];
    const float* L0b = (const float*)d_in[16];
    const float* L1W = (const float*)d_in[17];
    const float* L1b = (const float*)d_in[18];
    float* out = (float*)d_out;

    // ---- graph setup: mean, CSR by dst, edge-attention dots ----
    k_msum<<<256, 256>>>(ew);
    k_mfin<<<1, 256>>>();
    k_zero_cnt<<<(NN + 255) / 256, 256>>>();
    k_hist<<<(ET + 255) / 256, 256>>>(ei);
    k_scan<<<1, 1024>>>();
    k_zero_cnt<<<(NN + 255) / 256, 256>>>();
    k_scatter<<<(ET + 255) / 256, 256>>>(ei, ew);
    k_edot<<<1, 256>>>(We0, ae0, We1, ae1);

    dim3 g512(4, NP / 128);
    dim3 g128(1, NP / 128);

    // ---- GAT layer 0 ----
    tgemm<<<g512, 256>>>(x, 0, 0, W0, NN, HC, FIN);
    k_attn<<<(NN * NH + 7) / 8, 256>>>(as0, ad0);
    k_agg<<<(NN + 7) / 8, 256>>>(b0, 0);

    // ---- GAT layer 1 ----
    tgemm<<<g512, 256>>>(nullptr, 1, 0, W1, NN, HC, HC);
    k_attn<<<(NN * NH + 7) / 8, 256>>>(as1, ad1);
    k_agg<<<(NN + 7) / 8, 256>>>(b1, 4);

    // ---- MLP head ----
    tgemm<<<g128, 256>>>(nullptr, 1, 1, L0W, NN, FTS, HC);
    k_final<<<(NN + 7) / 8, 256>>>(L0b, L1W, L1b, out);
}

// round 6
// speedup vs baseline: 1.5634x; 1.1272x over previous
#include <cuda_runtime.h>
#include <cstdint>
#include <cuda_fp16.h>
#include <mma.h>
using namespace nvcuda;

#define NN  20000
#define NP  20096               // 157 * 128, padded row count for GEMM tiles
#define FIN 64
#define NH  4
#define NC  128
#define HC  512
#define NE  320000
#define ET  (NE + NN)
#define FTS 128
#define NBLK ((NN + 1023) / 1024)   // 20 scan blocks

// ---------------- scratch (device globals; no allocation allowed) ----------
__device__ __align__(16) float  g_bufH[(size_t)NP * HC];   // pre-bias h (fp32, GEMM out)
__device__ __align__(16) __half g_bufHh[(size_t)NP * HC];  // fp16 copy for gather
__device__ __align__(16) float  g_bufA[(size_t)NP * HC];   // layer output (post relu+bias)
__device__ __align__(16) float  g_bufC[(size_t)NP * FTS];  // head hidden (pre-bias/relu)
__device__ float g_asrc[NN * NH];
__device__ float g_adst[NN * NH];
__device__ float g_edot[8];           // [layer*4 + head]
__device__ int   g_rowptr[NN + 1];
__device__ int   g_cnt[NN];
__device__ int   g_bsum[32];
__device__ int   g_boff[32];
__device__ int   g_col[ET];
__device__ __align__(16) float g_ewt[ET];
__device__ float g_part[256];
__device__ float g_mean;

// ---------------- mean(edge_weights) --------------------------------------
__global__ void k_msum(const float* __restrict__ ew) {
    __shared__ float sh[256];
    float s = 0.f;
    for (int i = blockIdx.x * 256 + threadIdx.x; i < NE; i += 256 * 256) s += ew[i];
    sh[threadIdx.x] = s; __syncthreads();
    for (int off = 128; off; off >>= 1) {
        if (threadIdx.x < off) sh[threadIdx.x] += sh[threadIdx.x + off];
        __syncthreads();
    }
    if (threadIdx.x == 0) g_part[blockIdx.x] = sh[0];
}
__global__ void k_mfin() {
    __shared__ float sh[256];
    sh[threadIdx.x] = g_part[threadIdx.x]; __syncthreads();
    for (int off = 128; off; off >>= 1) {
        if (threadIdx.x < off) sh[threadIdx.x] += sh[threadIdx.x + off];
        __syncthreads();
    }
    if (threadIdx.x == 0) g_mean = sh[0] * (1.0f / NE);
}

// ---------------- CSR build ------------------------------------------------
__global__ void k_zero_cnt() {
    int i = blockIdx.x * blockDim.x + threadIdx.x;
    if (i < NN) g_cnt[i] = 0;
}
__global__ void k_hist(const int* __restrict__ ei) {
    int e = blockIdx.x * blockDim.x + threadIdx.x;
    if (e >= ET) return;
    int dst = (e < NE) ? ei[NE + e] : (e - NE);
    atomicAdd(&g_cnt[dst], 1);
}
// two-level scan: per-block exclusive scan + block totals
__global__ void k_scan1() {
    __shared__ int sh[1024];
    int t = threadIdx.x;
    int idx = blockIdx.x * 1024 + t;
    int v = (idx < NN) ? g_cnt[idx] : 0;
    sh[t] = v; __syncthreads();
    for (int off = 1; off < 1024; off <<= 1) {
        int x = (t >= off) ? sh[t - off] : 0;
        __syncthreads();
        sh[t] += x;
        __syncthreads();
    }
    if (idx < NN) g_rowptr[idx] = sh[t] - v;          // exclusive within block
    if (t == 1023) g_bsum[blockIdx.x] = sh[1023];
}
__global__ void k_scan2() {
    int t = threadIdx.x;                               // 32 threads
    int v = (t < NBLK) ? g_bsum[t] : 0;
    int incl = v;
    #pragma unroll
    for (int off = 1; off < 32; off <<= 1) {
        int x = __shfl_up_sync(0xffffffffu, incl, off);
        if (t >= off) incl += x;
    }
    if (t < NBLK) g_boff[t] = incl - v;
    if (t == 31) g_rowptr[NN] = incl;                  // grand total
}
__global__ void k_scan3() {
    int idx = blockIdx.x * blockDim.x + threadIdx.x;
    if (idx < NN) g_rowptr[idx] += g_boff[idx >> 10];
}
__global__ void k_scatter(const int* __restrict__ ei,
                          const float* __restrict__ ew) {
    int e = blockIdx.x * blockDim.x + threadIdx.x;
    if (e >= ET) return;
    int src, dst; float w;
    if (e < NE) { src = ei[e]; dst = ei[NE + e]; w = ew[e]; }
    else        { src = dst = e - NE; w = g_mean; }
    int pos = g_rowptr[dst] + atomicAdd(&g_cnt[dst], 1);
    g_col[pos] = src;
    g_ewt[pos] = w;
}

// ---------------- edge-attention dot precompute -----------------------------
__global__ void k_edot(const float* __restrict__ We0, const float* __restrict__ ae0,
                       const float* __restrict__ We1, const float* __restrict__ ae1) {
    int w = threadIdx.x >> 5, lane = threadIdx.x & 31;
    const float* We = (w < 4) ? We0 : We1;
    const float* ae = (w < 4) ? ae0 : ae1;
    int hh = w & 3;
    float s = 0.f;
    for (int c = lane; c < NC; c += 32) s += We[hh * NC + c] * ae[hh * NC + c];
    #pragma unroll
    for (int off = 16; off; off >>= 1) s += __shfl_xor_sync(0xffffffffu, s, off);
    if (lane == 0) g_edot[w] = s;
}

// ---------------- TF32 tensor-core GEMM: C = A[M,K] @ B[Nn,K]^T ------------
#define KC 16
__global__ void __launch_bounds__(256, 2)
tgemm(const float* __restrict__ Aext, int aSel, int cSel,
      const float* __restrict__ B, int M, int Nn, int K) {
    const float* __restrict__ A = aSel ? (const float*)g_bufA : Aext;
    float* __restrict__ Cm = cSel ? g_bufC : g_bufH;

    __shared__ float As[2][128][KC + 8];   // ld = 24
    __shared__ float Bs[2][128][KC + 8];

    int tid = threadIdx.x;
    int wid = tid >> 5;
    int row0 = blockIdx.y * 128, col0 = blockIdx.x * 128;
    int warp_m = (wid >> 2) * 64;
    int warp_n = (wid & 3) * 32;

    wmma::fragment<wmma::accumulator, 16, 16, 8, float> acc[4][2];
    #pragma unroll
    for (int i = 0; i < 4; i++)
        #pragma unroll
        for (int j = 0; j < 2; j++) wmma::fill_fragment(acc[i][j], 0.f);

    int r0 = tid >> 2;
    int kq = (tid & 3) << 2;
    int T = K / KC;

    {
        #pragma unroll
        for (int i = 0; i < 2; i++) {
            int r = r0 + i * 64;
            unsigned int sa = (unsigned int)__cvta_generic_to_shared(&As[0][r][kq]);
            const float* gp = A + (size_t)(row0 + r) * K + kq;
            if (row0 + r < M)
                asm volatile("cp.async.ca.shared.global [%0], [%1], 16;" :: "r"(sa), "l"(gp));
            else
                *(float4*)&As[0][r][kq] = make_float4(0.f, 0.f, 0.f, 0.f);
            unsigned int sb = (unsigned int)__cvta_generic_to_shared(&Bs[0][r][kq]);
            const float* gb = B + (size_t)(col0 + r) * K + kq;
            asm volatile("cp.async.ca.shared.global [%0], [%1], 16;" :: "r"(sb), "l"(gb));
        }
        asm volatile("cp.async.commit_group;");
    }

    for (int t = 0; t < T; t++) {
        int cur = t & 1;
        if (t + 1 < T) {
            int k0 = (t + 1) * KC, nxt = (t + 1) & 1;
            #pragma unroll
            for (int i = 0; i < 2; i++) {
                int r = r0 + i * 64;
                unsigned int sa = (unsigned int)__cvta_generic_to_shared(&As[nxt][r][kq]);
                const float* gp = A + (size_t)(row0 + r) * K + k0 + kq;
                if (row0 + r < M)
                    asm volatile("cp.async.ca.shared.global [%0], [%1], 16;" :: "r"(sa), "l"(gp));
                else
                    *(float4*)&As[nxt][r][kq] = make_float4(0.f, 0.f, 0.f, 0.f);
                unsigned int sb = (unsigned int)__cvta_generic_to_shared(&Bs[nxt][r][kq]);
                const float* gb = B + (size_t)(col0 + r) * K + k0 + kq;
                asm volatile("cp.async.ca.shared.global [%0], [%1], 16;" :: "r"(sb), "l"(gb));
            }
            asm volatile("cp.async.commit_group;");
            asm volatile("cp.async.wait_group 1;");
        } else {
            asm volatile("cp.async.wait_group 0;");
        }
        __syncthreads();

        #pragma unroll
        for (int kk = 0; kk < KC; kk += 8) {
            wmma::fragment<wmma::matrix_a, 16, 16, 8, wmma::precision::tf32, wmma::row_major> af[4];
            wmma::fragment<wmma::matrix_b, 16, 16, 8, wmma::precision::tf32, wmma::col_major> bf[2];
            #pragma unroll
            for (int i = 0; i < 4; i++) {
                wmma::load_matrix_sync(af[i], &As[cur][warp_m + i * 16][kk], KC + 8);
                #pragma unroll
                for (int e = 0; e < af[i].num_elements; e++)
                    af[i].x[e] = wmma::__float_to_tf32(af[i].x[e]);
            }
            #pragma unroll
            for (int j = 0; j < 2; j++) {
                wmma::load_matrix_sync(bf[j], &Bs[cur][warp_n + j * 16][kk], KC + 8);
                #pragma unroll
                for (int e = 0; e < bf[j].num_elements; e++)
                    bf[j].x[e] = wmma::__float_to_tf32(bf[j].x[e]);
            }
            #pragma unroll
            for (int i = 0; i < 4; i++)
                #pragma unroll
                for (int j = 0; j < 2; j++)
                    wmma::mma_sync(acc[i][j], af[i], bf[j], acc[i][j]);
        }
        __syncthreads();
    }

    #pragma unroll
    for (int i = 0; i < 4; i++)
        #pragma unroll
        for (int j = 0; j < 2; j++)
            wmma::store_matrix_sync(Cm + (size_t)(row0 + warp_m + i * 16) * Nn
                                       + col0 + warp_n + j * 16,
                                    acc[i][j], Nn, wmma::mem_row_major);
}

// ---------------- attention coefficients + fp16 h copy ---------------------
__global__ void k_attn(const float* __restrict__ a_s,
                       const float* __restrict__ a_d) {
    int w = (blockIdx.x * blockDim.x + threadIdx.x) >> 5;
    if (w >= NN * NH) return;
    int lane = threadIdx.x & 31;
    int n = w >> 2, hh = w & 3;
    const float4* hp = (const float4*)(g_bufH + (size_t)n * HC + hh * NC);
    const float4* sp = (const float4*)(a_s + hh * NC);
    const float4* dp = (const float4*)(a_d + hh * NC);
    float4 hv = hp[lane], sv = sp[lane], dv = dp[lane];

    // fp16 copy for the gather kernel
    __half2 h0 = __floats2half2_rn(hv.x, hv.y);
    __half2 h1 = __floats2half2_rn(hv.z, hv.w);
    uint2 pk;
    pk.x = *(unsigned int*)&h0;
    pk.y = *(unsigned int*)&h1;
    *(uint2*)(g_bufHh + (size_t)n * HC + hh * NC + lane * 4) = pk;

    float ps = hv.x * sv.x + hv.y * sv.y + hv.z * sv.z + hv.w * sv.w;
    float pd = hv.x * dv.x + hv.y * dv.y + hv.z * dv.z + hv.w * dv.w;
    #pragma unroll
    for (int off = 16; off; off >>= 1) {
        ps += __shfl_xor_sync(0xffffffffu, ps, off);
        pd += __shfl_xor_sync(0xffffffffu, pd, off);
    }
    if (lane == 0) { g_asrc[w] = ps; g_adst[w] = pd; }
}

// ---------------- per-dst softmax + fp16-gather aggregation ----------------
// One warp per dst. Logit lanes: edge slot = lane>>2, head = lane&3.
// Feature lanes: lane covers halfs [lane*8, lane*8+8) of each 256-half half-row;
// head of part A = lane<16 ? 0 : 1, part B = lane<16 ? 2 : 3.
__global__ void __launch_bounds__(256)
k_agg(const float* __restrict__ bias, int edotOff) {
    int w = (blockIdx.x * blockDim.x + threadIdx.x) >> 5;
    if (w >= NN) return;
    int lane = threadIdx.x & 31;
    int n = w;
    int beg = g_rowptr[n], end = g_rowptr[n + 1];
    int hh = lane & 3;
    float adn = g_adst[n * NH + hh];
    float ed = g_edot[edotOff + hh];

    float lmax = -1e30f;
    for (int i = beg + (lane >> 2); i < end; i += 8) {
        int s = g_col[i];
        float l = g_asrc[s * NH + hh] + adn + g_ewt[i] * ed;
        l = (l > 0.f) ? l : 0.2f * l;
        lmax = fmaxf(lmax, l);
    }
    #pragma unroll
    for (int off = 4; off < 32; off <<= 1)
        lmax = fmaxf(lmax, __shfl_xor_sync(0xffffffffu, lmax, off));

    float accA[8], accB[8];
    #pragma unroll
    for (int i = 0; i < 8; i++) { accA[i] = 0.f; accB[i] = 0.f; }
    float psum = 0.f;

    for (int base = beg; base < end; base += 8) {
        int i = base + (lane >> 2);
        float p = 0.f; int s = 0;
        if (i < end) {
            s = g_col[i];
            float l = g_asrc[s * NH + hh] + adn + g_ewt[i] * ed;
            l = (l > 0.f) ? l : 0.2f * l;
            p = __expf(l - lmax);
        }
        psum += p;
        int nb = min(8, end - base);
        for (int j = 0; j < nb; j++) {
            int   sj = __shfl_sync(0xffffffffu, s, j * 4);
            float p0 = __shfl_sync(0xffffffffu, p, j * 4 + 0);
            float p1 = __shfl_sync(0xffffffffu, p, j * 4 + 1);
            float p2 = __shfl_sync(0xffffffffu, p, j * 4 + 2);
            float p3 = __shfl_sync(0xffffffffu, p, j * 4 + 3);
            float pa = (lane < 16) ? p0 : p1;
            float pb = (lane < 16) ? p2 : p3;
            const uint4* hp = (const uint4*)(g_bufHh + (size_t)sj * HC);
            uint4 va = hp[lane];        // halfs [lane*8 .. +7] of head0/1 half
            uint4 vb = hp[lane + 32];   // halfs [256 + lane*8 ..] of head2/3 half
            float2 f;
            f = __half22float2(*(__half2*)&va.x); accA[0] += f.x * pa; accA[1] += f.y * pa;
            f = __half22float2(*(__half2*)&va.y); accA[2] += f.x * pa; accA[3] += f.y * pa;
            f = __half22float2(*(__half2*)&va.z); accA[4] += f.x * pa; accA[5] += f.y * pa;
            f = __half22float2(*(__half2*)&va.w); accA[6] += f.x * pa; accA[7] += f.y * pa;
            f = __half22float2(*(__half2*)&vb.x); accB[0] += f.x * pb; accB[1] += f.y * pb;
            f = __half22float2(*(__half2*)&vb.y); accB[2] += f.x * pb; accB[3] += f.y * pb;
            f = __half22float2(*(__half2*)&vb.z); accB[4] += f.x * pb; accB[5] += f.y * pb;
            f = __half22float2(*(__half2*)&vb.w); accB[6] += f.x * pb; accB[7] += f.y * pb;
        }
    }
    #pragma unroll
    for (int off = 4; off < 32; off <<= 1)
        psum += __shfl_xor_sync(0xffffffffu, psum, off);
    float s0 = 1.f / (__shfl_sync(0xffffffffu, psum, 0) + 1e-16f);
    float s1 = 1.f / (__shfl_sync(0xffffffffu, psum, 1) + 1e-16f);
    float s2 = 1.f / (__shfl_sync(0xffffffffu, psum, 2) + 1e-16f);
    float s3 = 1.f / (__shfl_sync(0xffffffffu, psum, 3) + 1e-16f);
    float sA = (lane < 16) ? s0 : s1;
    float sB = (lane < 16) ? s2 : s3;

    float4* op = (float4*)(g_bufA + (size_t)n * HC);
    const float4* bp = (const float4*)bias;
    float4 bv, o;
    // part A: float4 indices lane*2, lane*2+1 ; part B: +64
    bv = bp[lane * 2];
    o.x = fmaxf(accA[0] * sA + bv.x, 0.f); o.y = fmaxf(accA[1] * sA + bv.y, 0.f);
    o.z = fmaxf(accA[2] * sA + bv.z, 0.f); o.w = fmaxf(accA[3] * sA + bv.w, 0.f);
    op[lane * 2] = o;
    bv = bp[lane * 2 + 1];
    o.x = fmaxf(accA[4] * sA + bv.x, 0.f); o.y = fmaxf(accA[5] * sA + bv.y, 0.f);
    o.z = fmaxf(accA[6] * sA + bv.z, 0.f); o.w = fmaxf(accA[7] * sA + bv.w, 0.f);
    op[lane * 2 + 1] = o;
    bv = bp[64 + lane * 2];
    o.x = fmaxf(accB[0] * sB + bv.x, 0.f); o.y = fmaxf(accB[1] * sB + bv.y, 0.f);
    o.z = fmaxf(accB[2] * sB + bv.z, 0.f); o.w = fmaxf(accB[3] * sB + bv.w, 0.f);
    op[64 + lane * 2] = o;
    bv = bp[64 + lane * 2 + 1];
    o.x = fmaxf(accB[4] * sB + bv.x, 0.f); o.y = fmaxf(accB[5] * sB + bv.y, 0.f);
    o.z = fmaxf(accB[6] * sB + bv.z, 0.f); o.w = fmaxf(accB[7] * sB + bv.w, 0.f);
    op[64 + lane * 2 + 1] = o;
}

// ---------------- final head: out[n] = relu(c+b) . L1W + L1b ---------------
__global__ void k_final(const float* __restrict__ L0b,
                        const float* __restrict__ L1W, const float* __restrict__ L1b,
                        float* __restrict__ out) {
    int w = (blockIdx.x * blockDim.x + threadIdx.x) >> 5;
    if (w >= NN) return;
    int lane = threadIdx.x & 31;
    const float4* hp = (const float4*)(g_bufC + (size_t)w * FTS);
    const float4* bp = (const float4*)L0b;
    const float4* wp = (const float4*)L1W;
    float4 h = hp[lane], bb = bp[lane], ww = wp[lane];
    float s = fmaxf(h.x + bb.x, 0.f) * ww.x + fmaxf(h.y + bb.y, 0.f) * ww.y
            + fmaxf(h.z + bb.z, 0.f) * ww.z + fmaxf(h.w + bb.w, 0.f) * ww.w;
    #pragma unroll
    for (int off = 16; off; off >>= 1) s += __shfl_xor_sync(0xffffffffu, s, off);
    if (lane == 0) out[w] = s + L1b[0];
}

// ---------------- launch ----------------------------------------------------
extern "C" void kernel_launch(void* const* d_in, const int* in_sizes, int n_in,
                              void* d_out, int out_size) {
    const float* x   = (const float*)d_in[0];
    const int*   ei  = (const int*)d_in[1];
    const float* ew  = (const float*)d_in[2];
    const float* W0  = (const float*)d_in[3];
    const float* as0 = (const float*)d_in[4];
    const float* ad0 = (const float*)d_in[5];
    const float* We0 = (const float*)d_in[6];
    const float* ae0 = (const float*)d_in[7];
    const float* b0  = (const float*)d_in[8];
    const float* W1  = (const float*)d_in[9];
    const float* as1 = (const float*)d_in[10];
    const float* ad1 = (const float*)d_in[11];
    const float* We1 = (const float*)d_in[12];
    const float* ae1 = (const float*)d_in[13];
    const float* b1  = (const float*)d_in[14];
    const float* L0W = (const float*)d_in[15];
    const float* L0b = (const float*)d_in[16];
    const float* L1W = (const float*)d_in[17];
    const float* L1b = (const float*)d_in[18];
    float* out = (float*)d_out;

    // ---- graph setup: mean, CSR by dst, edge-attention dots ----
    k_msum<<<256, 256>>>(ew);
    k_mfin<<<1, 256>>>();
    k_zero_cnt<<<(NN + 255) / 256, 256>>>();
    k_hist<<<(ET + 255) / 256, 256>>>(ei);
    k_scan1<<<NBLK, 1024>>>();
    k_scan2<<<1, 32>>>();
    k_scan3<<<(NN + 255) / 256, 256>>>();
    k_zero_cnt<<<(NN + 255) / 256, 256>>>();
    k_scatter<<<(ET + 255) / 256, 256>>>(ei, ew);
    k_edot<<<1, 256>>>(We0, ae0, We1, ae1);

    dim3 g512(4, NP / 128);
    dim3 g128(1, NP / 128);

    // ---- GAT layer 0 ----
    tgemm<<<g512, 256>>>(x, 0, 0, W0, NN, HC, FIN);
    k_attn<<<(NN * NH + 7) / 8, 256>>>(as0, ad0);
    k_agg<<<(NN + 7) / 8, 256>>>(b0, 0);

    // ---- GAT layer 1 ----
    tgemm<<<g512, 256>>>(nullptr, 1, 0, W1, NN, HC, HC);
    k_attn<<<(NN * NH + 7) / 8, 256>>>(as1, ad1);
    k_agg<<<(NN + 7) / 8, 256>>>(b1, 4);

    // ---- MLP head ----
    tgemm<<<g128, 256>>>(nullptr, 1, 1, L0W, NN, FTS, HC);
    k_final<<<(NN + 7) / 8, 256>>>(L0b, L1W, L1b, out);
}

// round 7
// speedup vs baseline: 3.0261x; 1.9356x over previous
#include <cuda_runtime.h>
#include <cstdint>
#include <cuda_fp16.h>
#include <mma.h>
using namespace nvcuda;

#define NN  20000
#define NP  20096               // 157 * 128
#define FIN 64
#define NH  4
#define NC  128
#define HC  512
#define NE  320000
#define ET  (NE + NN)
#define FTS 128
#define NBLK ((NN + 1023) / 1024)

// ---------------- scratch ---------------------------------------------------
__device__ __align__(16) float  g_bufH[(size_t)NP * HC];    // layer GEMM out (fp32)
__device__ __align__(16) __half g_bufHh[(size_t)NP * HC];   // fp16 h for gather
__device__ __align__(16) __half g_bufAh[(size_t)NP * HC];   // layer output (fp16, GEMM A)
__device__ __align__(16) float  g_bufC[(size_t)NP * FTS];   // head hidden (fp32)
__device__ __align__(16) __half g_xh[(size_t)NP * FIN];     // fp16 x (padded, zeros)
__device__ __align__(16) __half g_W0h[HC * FIN];
__device__ __align__(16) __half g_W1h[HC * HC];
__device__ __align__(16) __half g_L0Wh[FTS * HC];
__device__ float g_asrc[NN * NH];
__device__ float g_adst[NN * NH];
__device__ float g_edot[8];
__device__ int   g_rowptr[NN + 1];
__device__ int   g_cnt[NN];
__device__ int   g_bsum[32];
__device__ int   g_boff[32];
__device__ int   g_col[ET];
__device__ __align__(16) float g_ewt[ET];
__device__ float g_part[256];
__device__ float g_mean;

// ---------------- fp32 -> fp16 conversion (vectorized x4) ------------------
// sel: 0 = g_xh, 1 = g_W0h, 2 = g_W1h, 3 = g_L0Wh
__global__ void k_tohalf(const float* __restrict__ src, int sel, int n4) {
    int i = blockIdx.x * blockDim.x + threadIdx.x;
    if (i >= n4) return;
    __half* dst = (sel == 0) ? g_xh : (sel == 1) ? g_W0h : (sel == 2) ? g_W1h : g_L0Wh;
    float4 v = ((const float4*)src)[i];
    __half2 a = __floats2half2_rn(v.x, v.y);
    __half2 b = __floats2half2_rn(v.z, v.w);
    uint2 pk; pk.x = *(unsigned int*)&a; pk.y = *(unsigned int*)&b;
    ((uint2*)dst)[i] = pk;
}

// ---------------- mean(edge_weights) ---------------------------------------
__global__ void k_msum(const float* __restrict__ ew) {
    __shared__ float sh[256];
    float s = 0.f;
    for (int i = blockIdx.x * 256 + threadIdx.x; i < NE; i += 256 * 256) s += ew[i];
    sh[threadIdx.x] = s; __syncthreads();
    for (int off = 128; off; off >>= 1) {
        if (threadIdx.x < off) sh[threadIdx.x] += sh[threadIdx.x + off];
        __syncthreads();
    }
    if (threadIdx.x == 0) g_part[blockIdx.x] = sh[0];
}
__global__ void k_mfin() {
    __shared__ float sh[256];
    sh[threadIdx.x] = g_part[threadIdx.x]; __syncthreads();
    for (int off = 128; off; off >>= 1) {
        if (threadIdx.x < off) sh[threadIdx.x] += sh[threadIdx.x + off];
        __syncthreads();
    }
    if (threadIdx.x == 0) g_mean = sh[0] * (1.0f / NE);
}

// ---------------- CSR build -------------------------------------------------
__global__ void k_zero_cnt() {
    int i = blockIdx.x * blockDim.x + threadIdx.x;
    if (i < NN) g_cnt[i] = 0;
}
__global__ void k_hist(const int* __restrict__ ei) {
    int e = blockIdx.x * blockDim.x + threadIdx.x;
    if (e >= ET) return;
    int dst = (e < NE) ? ei[NE + e] : (e - NE);
    atomicAdd(&g_cnt[dst], 1);
}
__global__ void k_scan1() {
    __shared__ int sh[1024];
    int t = threadIdx.x;
    int idx = blockIdx.x * 1024 + t;
    int v = (idx < NN) ? g_cnt[idx] : 0;
    sh[t] = v; __syncthreads();
    for (int off = 1; off < 1024; off <<= 1) {
        int x = (t >= off) ? sh[t - off] : 0;
        __syncthreads();
        sh[t] += x;
        __syncthreads();
    }
    if (idx < NN) g_rowptr[idx] = sh[t] - v;
    if (t == 1023) g_bsum[blockIdx.x] = sh[1023];
}
__global__ void k_scan2() {
    int t = threadIdx.x;
    int v = (t < NBLK) ? g_bsum[t] : 0;
    int incl = v;
    #pragma unroll
    for (int off = 1; off < 32; off <<= 1) {
        int x = __shfl_up_sync(0xffffffffu, incl, off);
        if (t >= off) incl += x;
    }
    if (t < NBLK) g_boff[t] = incl - v;
    if (t == 31) g_rowptr[NN] = incl;
}
__global__ void k_scan3() {        // also re-zeros g_cnt for scatter
    int idx = blockIdx.x * blockDim.x + threadIdx.x;
    if (idx < NN) {
        g_rowptr[idx] += g_boff[idx >> 10];
        g_cnt[idx] = 0;
    }
}
__global__ void k_scatter(const int* __restrict__ ei,
                          const float* __restrict__ ew) {
    int e = blockIdx.x * blockDim.x + threadIdx.x;
    if (e >= ET) return;
    int src, dst; float w;
    if (e < NE) { src = ei[e]; dst = ei[NE + e]; w = ew[e]; }
    else        { src = dst = e - NE; w = g_mean; }
    int pos = g_rowptr[dst] + atomicAdd(&g_cnt[dst], 1);
    g_col[pos] = src;
    g_ewt[pos] = w;
}

// ---------------- edge-attention dot precompute -----------------------------
__global__ void k_edot(const float* __restrict__ We0, const float* __restrict__ ae0,
                       const float* __restrict__ We1, const float* __restrict__ ae1) {
    int w = threadIdx.x >> 5, lane = threadIdx.x & 31;
    const float* We = (w < 4) ? We0 : We1;
    const float* ae = (w < 4) ? ae0 : ae1;
    int hh = w & 3;
    float s = 0.f;
    for (int c = lane; c < NC; c += 32) s += We[hh * NC + c] * ae[hh * NC + c];
    #pragma unroll
    for (int off = 16; off; off >>= 1) s += __shfl_xor_sync(0xffffffffu, s, off);
    if (lane == 0) g_edot[w] = s;
}

// ---------------- fp16 tensor-core GEMM: C = A[M,K] @ B[Nn,K]^T -------------
// aSel: 0 = g_xh, 1 = g_bufAh.   bSel: 0 = g_W0h, 1 = g_W1h, 2 = g_L0Wh.
// cSel: 0 = g_bufH, 1 = g_bufC.  A buffers padded to NP rows -> no bounds checks.
#define KCH 32
__global__ void __launch_bounds__(256, 2)
tgemm_h(int aSel, int bSel, int cSel, int Nn, int K) {
    const __half* __restrict__ A = aSel ? g_bufAh : g_xh;
    const __half* __restrict__ B = (bSel == 0) ? g_W0h : (bSel == 1) ? g_W1h : g_L0Wh;
    float* __restrict__ Cm = cSel ? g_bufC : g_bufH;

    __shared__ __half As[2][128][KCH + 8];   // ld = 40 halves
    __shared__ __half Bs[2][128][KCH + 8];

    int tid = threadIdx.x;
    int wid = tid >> 5;
    int row0 = blockIdx.y * 128, col0 = blockIdx.x * 128;
    int warp_m = (wid >> 2) * 64;
    int warp_n = (wid & 3) * 32;

    wmma::fragment<wmma::accumulator, 16, 16, 16, float> acc[4][2];
    #pragma unroll
    for (int i = 0; i < 4; i++)
        #pragma unroll
        for (int j = 0; j < 2; j++) wmma::fill_fragment(acc[i][j], 0.f);

    int r0 = tid >> 2;                 // 0..63 (+64)
    int kq = (tid & 3) << 3;           // 0,8,16,24 halves (16B chunks)
    int T = K / KCH;

    {
        #pragma unroll
        for (int i = 0; i < 2; i++) {
            int r = r0 + i * 64;
            unsigned int sa = (unsigned int)__cvta_generic_to_shared(&As[0][r][kq]);
            const __half* gp = A + (size_t)(row0 + r) * K + kq;
            asm volatile("cp.async.ca.shared.global [%0], [%1], 16;" :: "r"(sa), "l"(gp));
            unsigned int sb = (unsigned int)__cvta_generic_to_shared(&Bs[0][r][kq]);
            const __half* gb = B + (size_t)(col0 + r) * K + kq;
            asm volatile("cp.async.ca.shared.global [%0], [%1], 16;" :: "r"(sb), "l"(gb));
        }
        asm volatile("cp.async.commit_group;");
    }

    for (int t = 0; t < T; t++) {
        int cur = t & 1;
        if (t + 1 < T) {
            int k0 = (t + 1) * KCH, nxt = (t + 1) & 1;
            #pragma unroll
            for (int i = 0; i < 2; i++) {
                int r = r0 + i * 64;
                unsigned int sa = (unsigned int)__cvta_generic_to_shared(&As[nxt][r][kq]);
                const __half* gp = A + (size_t)(row0 + r) * K + k0 + kq;
                asm volatile("cp.async.ca.shared.global [%0], [%1], 16;" :: "r"(sa), "l"(gp));
                unsigned int sb = (unsigned int)__cvta_generic_to_shared(&Bs[nxt][r][kq]);
                const __half* gb = B + (size_t)(col0 + r) * K + k0 + kq;
                asm volatile("cp.async.ca.shared.global [%0], [%1], 16;" :: "r"(sb), "l"(gb));
            }
            asm volatile("cp.async.commit_group;");
            asm volatile("cp.async.wait_group 1;");
        } else {
            asm volatile("cp.async.wait_group 0;");
        }
        __syncthreads();

        #pragma unroll
        for (int kk = 0; kk < KCH; kk += 16) {
            wmma::fragment<wmma::matrix_a, 16, 16, 16, __half, wmma::row_major> af[4];
            wmma::fragment<wmma::matrix_b, 16, 16, 16, __half, wmma::col_major> bf[2];
            #pragma unroll
            for (int i = 0; i < 4; i++)
                wmma::load_matrix_sync(af[i], &As[cur][warp_m + i * 16][kk], KCH + 8);
            #pragma unroll
            for (int j = 0; j < 2; j++)
                wmma::load_matrix_sync(bf[j], &Bs[cur][warp_n + j * 16][kk], KCH + 8);
            #pragma unroll
            for (int i = 0; i < 4; i++)
                #pragma unroll
                for (int j = 0; j < 2; j++)
                    wmma::mma_sync(acc[i][j], af[i], bf[j], acc[i][j]);
        }
        __syncthreads();
    }

    #pragma unroll
    for (int i = 0; i < 4; i++)
        #pragma unroll
        for (int j = 0; j < 2; j++)
            wmma::store_matrix_sync(Cm + (size_t)(row0 + warp_m + i * 16) * Nn
                                       + col0 + warp_n + j * 16,
                                    acc[i][j], Nn, wmma::mem_row_major);
}

// ---------------- attention coefficients + fp16 h copy ----------------------
__global__ void k_attn(const float* __restrict__ a_s,
                       const float* __restrict__ a_d) {
    int w = (blockIdx.x * blockDim.x + threadIdx.x) >> 5;
    if (w >= NN * NH) return;
    int lane = threadIdx.x & 31;
    int n = w >> 2, hh = w & 3;
    const float4* hp = (const float4*)(g_bufH + (size_t)n * HC + hh * NC);
    const float4* sp = (const float4*)(a_s + hh * NC);
    const float4* dp = (const float4*)(a_d + hh * NC);
    float4 hv = hp[lane], sv = sp[lane], dv = dp[lane];

    __half2 h0 = __floats2half2_rn(hv.x, hv.y);
    __half2 h1 = __floats2half2_rn(hv.z, hv.w);
    uint2 pk;
    pk.x = *(unsigned int*)&h0;
    pk.y = *(unsigned int*)&h1;
    *(uint2*)(g_bufHh + (size_t)n * HC + hh * NC + lane * 4) = pk;

    float ps = hv.x * sv.x + hv.y * sv.y + hv.z * sv.z + hv.w * sv.w;
    float pd = hv.x * dv.x + hv.y * dv.y + hv.z * dv.z + hv.w * dv.w;
    #pragma unroll
    for (int off = 16; off; off >>= 1) {
        ps += __shfl_xor_sync(0xffffffffu, ps, off);
        pd += __shfl_xor_sync(0xffffffffu, pd, off);
    }
    if (lane == 0) { g_asrc[w] = ps; g_adst[w] = pd; }
}

// ---------------- per-dst softmax + fp16-gather aggregation -----------------
// Output written as fp16 to g_bufAh (feeds next GEMM).
__global__ void __launch_bounds__(256)
k_agg(const float* __restrict__ bias, int edotOff) {
    int w = (blockIdx.x * blockDim.x + threadIdx.x) >> 5;
    if (w >= NN) return;
    int lane = threadIdx.x & 31;
    int n = w;
    int beg = g_rowptr[n], end = g_rowptr[n + 1];
    int hh = lane & 3;
    float adn = g_adst[n * NH + hh];
    float ed = g_edot[edotOff + hh];

    float lmax = -1e30f;
    for (int i = beg + (lane >> 2); i < end; i += 8) {
        int s = g_col[i];
        float l = g_asrc[s * NH + hh] + adn + g_ewt[i] * ed;
        l = (l > 0.f) ? l : 0.2f * l;
        lmax = fmaxf(lmax, l);
    }
    #pragma unroll
    for (int off = 4; off < 32; off <<= 1)
        lmax = fmaxf(lmax, __shfl_xor_sync(0xffffffffu, lmax, off));

    float accA[8], accB[8];
    #pragma unroll
    for (int i = 0; i < 8; i++) { accA[i] = 0.f; accB[i] = 0.f; }
    float psum = 0.f;

    for (int base = beg; base < end; base += 8) {
        int i = base + (lane >> 2);
        float p = 0.f; int s = 0;
        if (i < end) {
            s = g_col[i];
            float l = g_asrc[s * NH + hh] + adn + g_ewt[i] * ed;
            l = (l > 0.f) ? l : 0.2f * l;
            p = __expf(l - lmax);
        }
        psum += p;
        int nb = min(8, end - base);
        for (int j = 0; j < nb; j++) {
            int   sj = __shfl_sync(0xffffffffu, s, j * 4);
            float p0 = __shfl_sync(0xffffffffu, p, j * 4 + 0);
            float p1 = __shfl_sync(0xffffffffu, p, j * 4 + 1);
            float p2 = __shfl_sync(0xffffffffu, p, j * 4 + 2);
            float p3 = __shfl_sync(0xffffffffu, p, j * 4 + 3);
            float pa = (lane < 16) ? p0 : p1;
            float pb = (lane < 16) ? p2 : p3;
            const uint4* hp = (const uint4*)(g_bufHh + (size_t)sj * HC);
            uint4 va = hp[lane];
            uint4 vb = hp[lane + 32];
            float2 f;
            f = __half22float2(*(__half2*)&va.x); accA[0] += f.x * pa; accA[1] += f.y * pa;
            f = __half22float2(*(__half2*)&va.y); accA[2] += f.x * pa; accA[3] += f.y * pa;
            f = __half22float2(*(__half2*)&va.z); accA[4] += f.x * pa; accA[5] += f.y * pa;
            f = __half22float2(*(__half2*)&va.w); accA[6] += f.x * pa; accA[7] += f.y * pa;
            f = __half22float2(*(__half2*)&vb.x); accB[0] += f.x * pb; accB[1] += f.y * pb;
            f = __half22float2(*(__half2*)&vb.y); accB[2] += f.x * pb; accB[3] += f.y * pb;
            f = __half22float2(*(__half2*)&vb.z); accB[4] += f.x * pb; accB[5] += f.y * pb;
            f = __half22float2(*(__half2*)&vb.w); accB[6] += f.x * pb; accB[7] += f.y * pb;
        }
    }
    #pragma unroll
    for (int off = 4; off < 32; off <<= 1)
        psum += __shfl_xor_sync(0xffffffffu, psum, off);
    float s0 = 1.f / (__shfl_sync(0xffffffffu, psum, 0) + 1e-16f);
    float s1 = 1.f / (__shfl_sync(0xffffffffu, psum, 1) + 1e-16f);
    float s2 = 1.f / (__shfl_sync(0xffffffffu, psum, 2) + 1e-16f);
    float s3 = 1.f / (__shfl_sync(0xffffffffu, psum, 3) + 1e-16f);
    float sA = (lane < 16) ? s0 : s1;
    float sB = (lane < 16) ? s2 : s3;

    const float4* bp = (const float4*)bias;
    float4 b0 = bp[lane * 2], b1 = bp[lane * 2 + 1];
    float4 b2 = bp[64 + lane * 2], b3 = bp[64 + lane * 2 + 1];
    float oa0 = fmaxf(accA[0] * sA + b0.x, 0.f), oa1 = fmaxf(accA[1] * sA + b0.y, 0.f);
    float oa2 = fmaxf(accA[2] * sA + b0.z, 0.f), oa3 = fmaxf(accA[3] * sA + b0.w, 0.f);
    float oa4 = fmaxf(accA[4] * sA + b1.x, 0.f), oa5 = fmaxf(accA[5] * sA + b1.y, 0.f);
    float oa6 = fmaxf(accA[6] * sA + b1.z, 0.f), oa7 = fmaxf(accA[7] * sA + b1.w, 0.f);
    float ob0 = fmaxf(accB[0] * sB + b2.x, 0.f), ob1 = fmaxf(accB[1] * sB + b2.y, 0.f);
    float ob2 = fmaxf(accB[2] * sB + b2.z, 0.f), ob3 = fmaxf(accB[3] * sB + b2.w, 0.f);
    float ob4 = fmaxf(accB[4] * sB + b3.x, 0.f), ob5 = fmaxf(accB[5] * sB + b3.y, 0.f);
    float ob6 = fmaxf(accB[6] * sB + b3.z, 0.f), ob7 = fmaxf(accB[7] * sB + b3.w, 0.f);

    uint4 pka, pkb;
    __half2 t;
    t = __floats2half2_rn(oa0, oa1); pka.x = *(unsigned int*)&t;
    t = __floats2half2_rn(oa2, oa3); pka.y = *(unsigned int*)&t;
    t = __floats2half2_rn(oa4, oa5); pka.z = *(unsigned int*)&t;
    t = __floats2half2_rn(oa6, oa7); pka.w = *(unsigned int*)&t;
    t = __floats2half2_rn(ob0, ob1); pkb.x = *(unsigned int*)&t;
    t = __floats2half2_rn(ob2, ob3); pkb.y = *(unsigned int*)&t;
    t = __floats2half2_rn(ob4, ob5); pkb.z = *(unsigned int*)&t;
    t = __floats2half2_rn(ob6, ob7); pkb.w = *(unsigned int*)&t;
    uint4* op = (uint4*)(g_bufAh + (size_t)n * HC);
    op[lane] = pka;
    op[lane + 32] = pkb;
}

// ---------------- final head ------------------------------------------------
__global__ void k_final(const float* __restrict__ L0b,
                        const float* __restrict__ L1W, const float* __restrict__ L1b,
                        float* __restrict__ out) {
    int w = (blockIdx.x * blockDim.x + threadIdx.x) >> 5;
    if (w >= NN) return;
    int lane = threadIdx.x & 31;
    const float4* hp = (const float4*)(g_bufC + (size_t)w * FTS);
    const float4* bp = (const float4*)L0b;
    const float4* wp = (const float4*)L1W;
    float4 h = hp[lane], bb = bp[lane], ww = wp[lane];
    float s = fmaxf(h.x + bb.x, 0.f) * ww.x + fmaxf(h.y + bb.y, 0.f) * ww.y
            + fmaxf(h.z + bb.z, 0.f) * ww.z + fmaxf(h.w + bb.w, 0.f) * ww.w;
    #pragma unroll
    for (int off = 16; off; off >>= 1) s += __shfl_xor_sync(0xffffffffu, s, off);
    if (lane == 0) out[w] = s + L1b[0];
}

// ---------------- launch ----------------------------------------------------
extern "C" void kernel_launch(void* const* d_in, const int* in_sizes, int n_in,
                              void* d_out, int out_size) {
    const float* x   = (const float*)d_in[0];
    const int*   ei  = (const int*)d_in[1];
    const float* ew  = (const float*)d_in[2];
    const float* W0  = (const float*)d_in[3];
    const float* as0 = (const float*)d_in[4];
    const float* ad0 = (const float*)d_in[5];
    const float* We0 = (const float*)d_in[6];
    const float* ae0 = (const float*)d_in[7];
    const float* b0  = (const float*)d_in[8];
    const float* W1  = (const float*)d_in[9];
    const float* as1 = (const float*)d_in[10];
    const float* ad1 = (const float*)d_in[11];
    const float* We1 = (const float*)d_in[12];
    const float* ae1 = (const float*)d_in[13];
    const float* b1  = (const float*)d_in[14];
    const float* L0W = (const float*)d_in[15];
    const float* L0b = (const float*)d_in[16];
    const float* L1W = (const float*)d_in[17];
    const float* L1b = (const float*)d_in[18];
    float* out = (float*)d_out;

    // ---- fp16 conversions ----
    k_tohalf<<<(NN * FIN / 4 + 255) / 256, 256>>>(x, 0, NN * FIN / 4);
    k_tohalf<<<(HC * FIN / 4 + 255) / 256, 256>>>(W0, 1, HC * FIN / 4);
    k_tohalf<<<(HC * HC / 4 + 255) / 256, 256>>>(W1, 2, HC * HC / 4);
    k_tohalf<<<(FTS * HC / 4 + 255) / 256, 256>>>(L0W, 3, FTS * HC / 4);

    // ---- graph setup ----
    k_msum<<<256, 256>>>(ew);
    k_mfin<<<1, 256>>>();
    k_zero_cnt<<<(NN + 255) / 256, 256>>>();
    k_hist<<<(ET + 255) / 256, 256>>>(ei);
    k_scan1<<<NBLK, 1024>>>();
    k_scan2<<<1, 32>>>();
    k_scan3<<<(NN + 255) / 256, 256>>>();
    k_scatter<<<(ET + 255) / 256, 256>>>(ei, ew);
    k_edot<<<1, 256>>>(We0, ae0, We1, ae1);

    dim3 g512(4, NP / 128);
    dim3 g128(1, NP / 128);

    // ---- GAT layer 0 ----
    tgemm_h<<<g512, 256>>>(0, 0, 0, HC, FIN);
    k_attn<<<(NN * NH + 7) / 8, 256>>>(as0, ad0);
    k_agg<<<(NN + 7) / 8, 256>>>(b0, 0);

    // ---- GAT layer 1 ----
    tgemm_h<<<g512, 256>>>(1, 1, 0, HC, HC);
    k_attn<<<(NN * NH + 7) / 8, 256>>>(as1, ad1);
    k_agg<<<(NN + 7) / 8, 256>>>(b1, 4);

    // ---- MLP head ----
    tgemm_h<<<g128, 256>>>(1, 2, 1, FTS, HC);
    k_final<<<(NN + 7) / 8, 256>>>(L0b, L1W, L1b, out);
}